// round 11
// baseline (speedup 1.0000x reference)
#include <cuda_runtime.h>
#include <cuda_bf16.h>

// out[a,b] = (softmax(X[b] @ X[a]^T) * mask[a,b]) @ X[b]
// X: (384,32,32) fp32; mask/out: (384,384,32,32) fp32.
//
// mma.sync (HMMA fallback) path; tcgen05 unreachable (compute_103 PTX).
// R11: column permutation pi: fragment position (j,c,i) <-> true col 8c+2j+i.
//  - QK B operand: Xa rows permuted by pi (row-permuted staging).
//  - AV B operand: Xb copy with rows permuted by pi (k-dim, matches P) AND
//    u32 column-pairs permuted by the pair-transpose (n-dim) -- this was the
//    missing piece in R8/R10 (output columns were scrambled).
// Lane-quad c then owns contiguous true cols [8c,8c+8) of qk/mask/out, so
// mask/out move via LDG/STG.128 (dense 128B lines, half the L1 wavefronts).

#define NN 384
#define RS   80          // smem row stride (bytes)
#define BLKB (32 * RS)   // one 32-row array: 2560 B

typedef unsigned int u32;

// [hi 64B | lo 64B] per row, 384*32 rows = 1.5 MB (L2-resident scratch)
__device__ uint4 Xsplit[384 * 32 * 8];

static __device__ __forceinline__ u32 smem_u32(const void* p) {
    u32 a;
    asm("{ .reg .u64 t; cvta.to.shared.u64 t, %1; cvt.u32.u64 %0, t; }" : "=r"(a) : "l"(p));
    return a;
}

#define LDM4(r, addr)                                                                   \
    asm volatile("ldmatrix.sync.aligned.m8n8.x4.shared.b16 {%0,%1,%2,%3}, [%4];"        \
                 : "=r"((r)[0]), "=r"((r)[1]), "=r"((r)[2]), "=r"((r)[3]) : "r"(addr))

#define LDM4T(r, addr)                                                                  \
    asm volatile("ldmatrix.sync.aligned.m8n8.x4.trans.shared.b16 {%0,%1,%2,%3}, [%4];"  \
                 : "=r"((r)[0]), "=r"((r)[1]), "=r"((r)[2]), "=r"((r)[3]) : "r"(addr))

#define MMA(c, a, b0, b1)                                                               \
    asm volatile("mma.sync.aligned.m16n8k16.row.col.f32.bf16.bf16.f32 "                 \
                 "{%0,%1,%2,%3}, {%4,%5,%6,%7}, {%8,%9}, {%0,%1,%2,%3};"                \
                 : "+f"((c)[0]), "+f"((c)[1]), "+f"((c)[2]), "+f"((c)[3])               \
                 : "r"((a)[0]), "r"((a)[1]), "r"((a)[2]), "r"((a)[3]), "r"(b0), "r"(b1))

static __device__ __forceinline__ u32 pk_bf16(float lo, float hi) {
    u32 r;  // low half <- 'lo' (even element)
    asm("cvt.rn.bf16x2.f32 %0, %1, %2;" : "=r"(r) : "f"(hi), "f"(lo));
    return r;
}
static __device__ __forceinline__ float bf16_rt(float x) {
    return __bfloat162float(__float2bfloat16(x));
}

// pi: position p = 8j+2c+i  ->  true index 8c+2j+i  (involution)
static __device__ __forceinline__ int perm(int p) {
    return 8 * ((p >> 1) & 3) + 2 * (p >> 3) + (p & 1);
}

// exp via deg-5 2^f poly; FMA pipe only.
static __device__ __forceinline__ float fexp(float x) {
    x = fmaxf(x, -87.0f);
    const float z = x * 1.4426950408889634f;
    const int   i = __float2int_rn(z);
    const float f = z - __int2float_rn(i);
    float p = 0.0013333558f;
    p = fmaf(p, f, 0.0096181291f);
    p = fmaf(p, f, 0.0555041087f);
    p = fmaf(p, f, 0.2402265070f);
    p = fmaf(p, f, 0.6931471806f);
    p = fmaf(p, f, 1.0f);
    return p * __int_as_float((i + 127) << 23);
}

// ---- prep: split all X rows into bf16 hi/lo once ----
__global__ __launch_bounds__(128)
void prep_kernel(const float* __restrict__ x1) {
    const int idx = blockIdx.x * 128 + threadIdx.x;   // row 0..12287
    const float4* src = (const float4*)(x1 + (size_t)idx * 32);
    float v[32];
    #pragma unroll
    for (int j = 0; j < 8; j++) {
        const float4 q = src[j];
        v[4 * j] = q.x; v[4 * j + 1] = q.y; v[4 * j + 2] = q.z; v[4 * j + 3] = q.w;
    }
    uint4* dst = Xsplit + (size_t)idx * 8;
    #pragma unroll
    for (int c = 0; c < 4; c++) {
        const float* g = v + 8 * c;
        uint4 hv, lv;
        hv.x = pk_bf16(g[0], g[1]); hv.y = pk_bf16(g[2], g[3]);
        hv.z = pk_bf16(g[4], g[5]); hv.w = pk_bf16(g[6], g[7]);
        float r[8];
        #pragma unroll
        for (int i = 0; i < 8; i++) r[i] = g[i] - bf16_rt(g[i]);
        lv.x = pk_bf16(r[0], r[1]); lv.y = pk_bf16(r[2], r[3]);
        lv.z = pk_bf16(r[4], r[5]); lv.w = pk_bf16(r[6], r[7]);
        dst[c] = hv;
        dst[4 + c] = lv;
    }
}

// smem array indices: H at 2k, L at 2k+1
#define A_XB(b)  ((b) * 2)        // Xb identity rows (QK A operand)
#define A_XAP(a) (4 + (a) * 2)    // Xa pi-row-permuted (QK B operand)
#define A_XBP(b) (8 + (b) * 2)    // Xb pi-row + pair-transposed cols (AV B)

static __device__ __forceinline__ void stage_row(char* sm, int arr, int l,
                                                 const uint4* g) {
    char* H = sm + arr * BLKB + l * RS;
    char* L = H + BLKB;
    const int rot = l >> 3;
    #pragma unroll
    for (int c = 0; c < 4; c++) {
        const int cc = (c + rot) & 3;
        *(uint4*)(H + cc * 16) = g[cc];
        *(uint4*)(L + cc * 16) = g[4 + cc];
    }
}

// stage with u32 column-pair transpose: out u32 slot 4j+c <- src u32 4c+j.
// Output chunk cc = src u32s {cc, cc+4, cc+8, cc+12} (per hi/lo half).
static __device__ __forceinline__ void stage_row_ct(char* sm, int arr, int l,
                                                    const u32* hs) {
    char* H = sm + arr * BLKB + l * RS;
    char* L = H + BLKB;
    const int rot = l >> 3;
    #pragma unroll
    for (int c = 0; c < 4; c++) {
        const int cc = (c + rot) & 3;
        *(uint4*)(H + cc * 16) = make_uint4(hs[cc], hs[cc + 4], hs[cc + 8], hs[cc + 12]);
        *(uint4*)(L + cc * 16) = make_uint4(hs[16 + cc], hs[20 + cc], hs[24 + cc], hs[28 + cc]);
    }
}

__global__ __launch_bounds__(128, 7)
void attn_mma_kernel(const float* __restrict__ mask,
                     float* __restrict__ out) {
    __shared__ __align__(16) char sm[12 * BLKB];   // 30720 B

    const int t = threadIdx.x;
    const int w = t >> 5;
    const int l = t & 31;
    const int bx = blockIdx.x, by = blockIdx.y;
    const int pl = perm(l);

    // ---- staging ----
    if (w < 2) {
        // Xb identity (QK A) + Xb pi-rows/pair-transposed-cols (AV B)
        const uint4* g0 = Xsplit + ((size_t)(2 * bx + w) * 32 + l) * 8;
        const u32*   g1 = (const u32*)(Xsplit + ((size_t)(2 * bx + w) * 32 + pl) * 8);
        stage_row(sm, A_XB(w), l, g0);
        stage_row_ct(sm, A_XBP(w), l, g1);
    } else {
        // Xa pi-row-permuted (QK B); a-block = w-2
        const uint4* g = Xsplit + ((size_t)(2 * by + (w - 2)) * 32 + pl) * 8;
        stage_row(sm, A_XAP(w - 2), l, g);
    }
    __syncthreads();

    // ---- per-warp pair ----
    const int ai = w >> 1, bi = w & 1;
    const int a = 2 * by + ai, b = 2 * bx + bi;
    const size_t blkoff = ((size_t)a * NN + b) * 1024;

    const u32 sb = smem_u32(sm);
    const u32 XbH = sb + A_XB(bi) * BLKB,   XbL = XbH + BLKB;
    const u32 XaH = sb + A_XAP(ai) * BLKB,  XaL = XaH + BLKB;
    const u32 XtH = sb + A_XBP(bi) * BLKB,  XtL = XtH + BLKB;

    // ldmatrix per-lane offsets (consecutive-row patterns, conflict-free)
    const u32 aoff = (((l >> 3) & 1) * 8 + (l & 7)) * RS + ((l >> 4) & 1) * 16;
    const u32 boff = ((l >> 4) * 8 + (l & 7)) * RS + ((l >> 3) & 1) * 16;
    const u32 toff = (l & 15) * RS + ((l >> 4) & 1) * 16;

    // mask base: lane-quad c owns true cols [8c, 8c+8) of row (l>>2) per group
    const float* mbase = mask + blkoff + (size_t)(l >> 2) * 32 + 8 * (l & 3);

    // mask prefetch FIRST HALF (groups 0,1): float4 pairs, dense 128B lines
    float4 m4[4][2];
    #pragma unroll
    for (int g = 0; g < 2; g++) {
        m4[g][0] = *(const float4*)(mbase + (size_t)(8 * g) * 32);
        m4[g][1] = *(const float4*)(mbase + (size_t)(8 * g) * 32 + 4);
    }

    // ---- QK: 3-term bf16 split; B operand from pi-row-permuted Xa ----
    float c[2][4][4];
    #pragma unroll
    for (int mt = 0; mt < 2; mt++)
        #pragma unroll
        for (int j = 0; j < 4; j++)
            c[mt][j][0] = c[mt][j][1] = c[mt][j][2] = c[mt][j][3] = 0.f;

    #pragma unroll
    for (int kt = 0; kt < 2; kt++) {
        u32 AH[2][4], AL[2][4], BH[2][4], BL[2][4];
        LDM4(AH[0], XbH + kt * 32 + aoff);
        LDM4(AH[1], XbH + 1280 + kt * 32 + aoff);
        LDM4(AL[0], XbL + kt * 32 + aoff);
        LDM4(AL[1], XbL + 1280 + kt * 32 + aoff);
        LDM4(BH[0], XaH + kt * 32 + boff);
        LDM4(BH[1], XaH + 1280 + kt * 32 + boff);
        LDM4(BL[0], XaL + kt * 32 + boff);
        LDM4(BL[1], XaL + 1280 + kt * 32 + boff);
        #pragma unroll
        for (int mt = 0; mt < 2; mt++)
            #pragma unroll
            for (int j = 0; j < 4; j++) {
                const int jp = j >> 1, s = (j & 1) * 2;
                MMA(c[mt][j], AH[mt], BH[jp][s], BH[jp][s + 1]);
                MMA(c[mt][j], AL[mt], BH[jp][s], BH[jp][s + 1]);
                MMA(c[mt][j], AH[mt], BL[jp][s], BL[jp][s + 1]);
            }
    }

    // mask prefetch SECOND HALF (groups 2,3)
    #pragma unroll
    for (int g = 2; g < 4; g++) {
        m4[g][0] = *(const float4*)(mbase + (size_t)(8 * g) * 32);
        m4[g][1] = *(const float4*)(mbase + (size_t)(8 * g) * 32 + 4);
    }

    // ---- softmax (sum over permuted positions == sum over row) + dropout ----
    #pragma unroll
    for (int mt = 0; mt < 2; mt++)
        #pragma unroll
        for (int h = 0; h < 2; h++) {
            float s = 0.f;
            #pragma unroll
            for (int j = 0; j < 4; j++)
                #pragma unroll
                for (int i = 0; i < 2; i++) {
                    const float e = fexp(c[mt][j][2 * h + i]);
                    c[mt][j][2 * h + i] = e;
                    s += e;
                }
            s += __shfl_xor_sync(0xffffffffu, s, 1);
            s += __shfl_xor_sync(0xffffffffu, s, 2);
            const float inv = __fdividef(1.0f, s);
            // position (j,i) holds true col 8c+2j+i == float index 2j+i of m4
            const float* mf = (const float*)&m4[2 * mt + h][0];
            #pragma unroll
            for (int j = 0; j < 4; j++)
                #pragma unroll
                for (int i = 0; i < 2; i++)
                    c[mt][j][2 * h + i] *= inv * mf[2 * j + i];
        }

    // ---- AV: O = P @ Xb; B rows pi-permuted (k matches P), cols transposed
    //      (n) so output position p holds true col perm(p) ----
    float o[2][4][4];
    #pragma unroll
    for (int mt = 0; mt < 2; mt++)
        #pragma unroll
        for (int j = 0; j < 4; j++)
            o[mt][j][0] = o[mt][j][1] = o[mt][j][2] = o[mt][j][3] = 0.f;

    #pragma unroll
    for (int kt = 0; kt < 2; kt++) {
        u32 PH[2][4], PL[2][4];
        #pragma unroll
        for (int mt = 0; mt < 2; mt++) {
            const float* d0 = c[mt][2 * kt];
            const float* d1 = c[mt][2 * kt + 1];
            PH[mt][0] = pk_bf16(d0[0], d0[1]);
            PH[mt][1] = pk_bf16(d0[2], d0[3]);
            PH[mt][2] = pk_bf16(d1[0], d1[1]);
            PH[mt][3] = pk_bf16(d1[2], d1[3]);
            PL[mt][0] = pk_bf16(d0[0] - bf16_rt(d0[0]), d0[1] - bf16_rt(d0[1]));
            PL[mt][1] = pk_bf16(d0[2] - bf16_rt(d0[2]), d0[3] - bf16_rt(d0[3]));
            PL[mt][2] = pk_bf16(d1[0] - bf16_rt(d1[0]), d1[1] - bf16_rt(d1[1]));
            PL[mt][3] = pk_bf16(d1[2] - bf16_rt(d1[2]), d1[3] - bf16_rt(d1[3]));
        }
        u32 BH[2][4], BL[2][4];
        LDM4T(BH[0], XtH + kt * 1280 + toff);
        LDM4T(BH[1], XtH + kt * 1280 + 32 + toff);
        LDM4T(BL[0], XtL + kt * 1280 + toff);
        LDM4T(BL[1], XtL + kt * 1280 + 32 + toff);
        #pragma unroll
        for (int mt = 0; mt < 2; mt++)
            #pragma unroll
            for (int j = 0; j < 4; j++) {
                const int jp = j >> 1, s = (j & 1) * 2;
                MMA(o[mt][j], PH[mt], BH[jp][s], BH[jp][s + 1]);
                MMA(o[mt][j], PL[mt], BH[jp][s], BH[jp][s + 1]);
                MMA(o[mt][j], PH[mt], BL[jp][s], BL[jp][s + 1]);
            }
    }

    // ---- output: lane-quad owns true cols [8c,8c+8) -> STG.128 pairs ----
    #pragma unroll
    for (int mt = 0; mt < 2; mt++)
        #pragma unroll
        for (int h = 0; h < 2; h++) {
            float* orow = out + blkoff + (size_t)(16 * mt + 8 * h + (l >> 2)) * 32 + 8 * (l & 3);
            *(float4*)(orow)     = make_float4(o[mt][0][2 * h], o[mt][0][2 * h + 1],
                                               o[mt][1][2 * h], o[mt][1][2 * h + 1]);
            *(float4*)(orow + 4) = make_float4(o[mt][2][2 * h], o[mt][2][2 * h + 1],
                                               o[mt][3][2 * h], o[mt][3][2 * h + 1]);
        }
}

extern "C" void kernel_launch(void* const* d_in, const int* in_sizes, int n_in,
                              void* d_out, int out_size) {
    const float* x1   = (const float*)d_in[0];   // (1,384,32,32)
    const float* mask = (const float*)d_in[1];   // (384,384,32,32)
    float* out = (float*)d_out;                  // (384,384,32,32)
    (void)in_sizes; (void)n_in; (void)out_size;

    prep_kernel<<<96, 128>>>(x1);                       // 12288 rows
    dim3 grid(NN / 2, NN / 2, 1);                       // 4 pairs per CTA
    attn_mma_kernel<<<grid, 128>>>(mask, out);
}

// round 14
// speedup vs baseline: 1.1327x; 1.1327x over previous
#include <cuda_runtime.h>
#include <cuda_bf16.h>

// out[a,b] = (softmax(X[b] @ X[a]^T) * mask[a,b]) @ X[b]
// X: (384,32,32) fp32; mask/out: (384,384,32,32) fp32.
//
// mma.sync (HMMA fallback) path; tcgen05 unreachable (compute_103 PTX).
// R12: column permutation pi (validated in R11) with the u32 pair-transpose
// hoisted into the prep kernel (XsplitCT), so ALL main-kernel staging is
// vectorized uint4 row copies. Lane-quad c owns contiguous true cols
// [8c,8c+8) of qk/mask/out -> mask/out via dense LDG/STG.128.

#define NN 384
#define RS   80          // smem row stride (bytes)
#define BLKB (32 * RS)   // one 32-row array: 2560 B

typedef unsigned int u32;

// [hi 64B | lo 64B] per row, 384*32 rows = 1.5 MB each (L2-resident scratch)
__device__ uint4 Xsplit[384 * 32 * 8];    // natural column order
__device__ uint4 XsplitCT[384 * 32 * 8];  // u32 column-pairs 4x4-transposed

static __device__ __forceinline__ u32 smem_u32(const void* p) {
    u32 a;
    asm("{ .reg .u64 t; cvta.to.shared.u64 t, %1; cvt.u32.u64 %0, t; }" : "=r"(a) : "l"(p));
    return a;
}

#define LDM4(r, addr)                                                                   \
    asm volatile("ldmatrix.sync.aligned.m8n8.x4.shared.b16 {%0,%1,%2,%3}, [%4];"        \
                 : "=r"((r)[0]), "=r"((r)[1]), "=r"((r)[2]), "=r"((r)[3]) : "r"(addr))

#define LDM4T(r, addr)                                                                  \
    asm volatile("ldmatrix.sync.aligned.m8n8.x4.trans.shared.b16 {%0,%1,%2,%3}, [%4];"  \
                 : "=r"((r)[0]), "=r"((r)[1]), "=r"((r)[2]), "=r"((r)[3]) : "r"(addr))

#define MMA(c, a, b0, b1)                                                               \
    asm volatile("mma.sync.aligned.m16n8k16.row.col.f32.bf16.bf16.f32 "                 \
                 "{%0,%1,%2,%3}, {%4,%5,%6,%7}, {%8,%9}, {%0,%1,%2,%3};"                \
                 : "+f"((c)[0]), "+f"((c)[1]), "+f"((c)[2]), "+f"((c)[3])               \
                 : "r"((a)[0]), "r"((a)[1]), "r"((a)[2]), "r"((a)[3]), "r"(b0), "r"(b1))

static __device__ __forceinline__ u32 pk_bf16(float lo, float hi) {
    u32 r;  // low half <- 'lo' (even element)
    asm("cvt.rn.bf16x2.f32 %0, %1, %2;" : "=r"(r) : "f"(hi), "f"(lo));
    return r;
}
static __device__ __forceinline__ float bf16_rt(float x) {
    return __bfloat162float(__float2bfloat16(x));
}

// pi: position p = 8j+2c+i  ->  true index 8c+2j+i  (involution)
static __device__ __forceinline__ int perm(int p) {
    return 8 * ((p >> 1) & 3) + 2 * (p >> 3) + (p & 1);
}

// exp via deg-5 2^f poly; FMA pipe only.
static __device__ __forceinline__ float fexp(float x) {
    x = fmaxf(x, -87.0f);
    const float z = x * 1.4426950408889634f;
    const int   i = __float2int_rn(z);
    const float f = z - __int2float_rn(i);
    float p = 0.0013333558f;
    p = fmaf(p, f, 0.0096181291f);
    p = fmaf(p, f, 0.0555041087f);
    p = fmaf(p, f, 0.2402265070f);
    p = fmaf(p, f, 0.6931471806f);
    p = fmaf(p, f, 1.0f);
    return p * __int_as_float((i + 127) << 23);
}

// ---- prep: split rows into bf16 hi/lo; also write pair-transposed copy ----
__global__ __launch_bounds__(128)
void prep_kernel(const float* __restrict__ x1) {
    const int idx = blockIdx.x * 128 + threadIdx.x;   // row 0..12287
    const float4* src = (const float4*)(x1 + (size_t)idx * 32);
    float v[32], r[32];
    #pragma unroll
    for (int j = 0; j < 8; j++) {
        const float4 q = src[j];
        v[4 * j] = q.x; v[4 * j + 1] = q.y; v[4 * j + 2] = q.z; v[4 * j + 3] = q.w;
    }
    #pragma unroll
    for (int i = 0; i < 32; i++) r[i] = v[i] - bf16_rt(v[i]);

    uint4* dst = Xsplit + (size_t)idx * 8;
    uint4* dct = XsplitCT + (size_t)idx * 8;
    #pragma unroll
    for (int c = 0; c < 4; c++) {
        const float* g = v + 8 * c;
        const float* h = r + 8 * c;
        dst[c]     = make_uint4(pk_bf16(g[0], g[1]), pk_bf16(g[2], g[3]),
                                pk_bf16(g[4], g[5]), pk_bf16(g[6], g[7]));
        dst[4 + c] = make_uint4(pk_bf16(h[0], h[1]), pk_bf16(h[2], h[3]),
                                pk_bf16(h[4], h[5]), pk_bf16(h[6], h[7]));
        // transposed: chunk c slot j holds src u32-pair 4j+c = floats (8j+2c, 8j+2c+1)
        dct[c]     = make_uint4(pk_bf16(v[2 * c], v[2 * c + 1]),
                                pk_bf16(v[8 + 2 * c], v[8 + 2 * c + 1]),
                                pk_bf16(v[16 + 2 * c], v[16 + 2 * c + 1]),
                                pk_bf16(v[24 + 2 * c], v[24 + 2 * c + 1]));
        dct[4 + c] = make_uint4(pk_bf16(r[2 * c], r[2 * c + 1]),
                                pk_bf16(r[8 + 2 * c], r[8 + 2 * c + 1]),
                                pk_bf16(r[16 + 2 * c], r[16 + 2 * c + 1]),
                                pk_bf16(r[24 + 2 * c], r[24 + 2 * c + 1]));
    }
}

// smem array indices: H at 2k, L at 2k+1
#define A_XB(b)  ((b) * 2)        // Xb identity rows (QK A operand)
#define A_XAP(a) (4 + (a) * 2)    // Xa pi-row-permuted (QK B operand)
#define A_XBP(b) (8 + (b) * 2)    // XsplitCT rows pi-permuted (AV B operand)

static __device__ __forceinline__ void stage_row(char* sm, int arr, int l,
                                                 const uint4* g) {
    char* H = sm + arr * BLKB + l * RS;
    char* L = H + BLKB;
    const int rot = l >> 3;
    #pragma unroll
    for (int c = 0; c < 4; c++) {
        const int cc = (c + rot) & 3;
        *(uint4*)(H + cc * 16) = g[cc];
        *(uint4*)(L + cc * 16) = g[4 + cc];
    }
}

__global__ __launch_bounds__(128, 7)
void attn_mma_kernel(const float* __restrict__ mask,
                     float* __restrict__ out) {
    __shared__ __align__(16) char sm[12 * BLKB];   // 30720 B

    const int t = threadIdx.x;
    const int w = t >> 5;
    const int l = t & 31;
    const int bx = blockIdx.x, by = blockIdx.y;
    const int pl = perm(l);

    // ---- staging: all vectorized uint4 row copies ----
    if (w < 2) {
        const uint4* g0 = Xsplit   + ((size_t)(2 * bx + w) * 32 + l) * 8;
        const uint4* g1 = XsplitCT + ((size_t)(2 * bx + w) * 32 + pl) * 8;
        stage_row(sm, A_XB(w), l, g0);
        stage_row(sm, A_XBP(w), l, g1);
    } else {
        const uint4* g = Xsplit + ((size_t)(2 * by + (w - 2)) * 32 + pl) * 8;
        stage_row(sm, A_XAP(w - 2), l, g);
    }
    __syncthreads();

    // ---- per-warp pair ----
    const int ai = w >> 1, bi = w & 1;
    const int a = 2 * by + ai, b = 2 * bx + bi;
    const size_t blkoff = ((size_t)a * NN + b) * 1024;

    const u32 sb = smem_u32(sm);
    const u32 XbH = sb + A_XB(bi) * BLKB,   XbL = XbH + BLKB;
    const u32 XaH = sb + A_XAP(ai) * BLKB,  XaL = XaH + BLKB;
    const u32 XtH = sb + A_XBP(bi) * BLKB,  XtL = XtH + BLKB;

    // ldmatrix per-lane offsets (consecutive-row patterns, conflict-free)
    const u32 aoff = (((l >> 3) & 1) * 8 + (l & 7)) * RS + ((l >> 4) & 1) * 16;
    const u32 boff = ((l >> 4) * 8 + (l & 7)) * RS + ((l >> 3) & 1) * 16;
    const u32 toff = (l & 15) * RS + ((l >> 4) & 1) * 16;

    // mask base: lane-quad c owns true cols [8c, 8c+8) of row (l>>2) per group
    const float* mbase = mask + blkoff + (size_t)(l >> 2) * 32 + 8 * (l & 3);

    // mask prefetch FIRST HALF (groups 0,1): dense 128B lines
    float4 m4[4][2];
    #pragma unroll
    for (int g = 0; g < 2; g++) {
        m4[g][0] = *(const float4*)(mbase + (size_t)(8 * g) * 32);
        m4[g][1] = *(const float4*)(mbase + (size_t)(8 * g) * 32 + 4);
    }

    // ---- QK: 3-term bf16 split; B operand from pi-row-permuted Xa ----
    float c[2][4][4];
    #pragma unroll
    for (int mt = 0; mt < 2; mt++)
        #pragma unroll
        for (int j = 0; j < 4; j++)
            c[mt][j][0] = c[mt][j][1] = c[mt][j][2] = c[mt][j][3] = 0.f;

    #pragma unroll
    for (int kt = 0; kt < 2; kt++) {
        u32 AH[2][4], AL[2][4], BH[2][4], BL[2][4];
        LDM4(AH[0], XbH + kt * 32 + aoff);
        LDM4(AH[1], XbH + 1280 + kt * 32 + aoff);
        LDM4(AL[0], XbL + kt * 32 + aoff);
        LDM4(AL[1], XbL + 1280 + kt * 32 + aoff);
        LDM4(BH[0], XaH + kt * 32 + boff);
        LDM4(BH[1], XaH + 1280 + kt * 32 + boff);
        LDM4(BL[0], XaL + kt * 32 + boff);
        LDM4(BL[1], XaL + 1280 + kt * 32 + boff);
        #pragma unroll
        for (int mt = 0; mt < 2; mt++)
            #pragma unroll
            for (int j = 0; j < 4; j++) {
                const int jp = j >> 1, s = (j & 1) * 2;
                MMA(c[mt][j], AH[mt], BH[jp][s], BH[jp][s + 1]);
                MMA(c[mt][j], AL[mt], BH[jp][s], BH[jp][s + 1]);
                MMA(c[mt][j], AH[mt], BL[jp][s], BL[jp][s + 1]);
            }
    }

    // mask prefetch SECOND HALF (groups 2,3)
    #pragma unroll
    for (int g = 2; g < 4; g++) {
        m4[g][0] = *(const float4*)(mbase + (size_t)(8 * g) * 32);
        m4[g][1] = *(const float4*)(mbase + (size_t)(8 * g) * 32 + 4);
    }

    // ---- softmax (sum over permuted positions == sum over row) + dropout ----
    #pragma unroll
    for (int mt = 0; mt < 2; mt++)
        #pragma unroll
        for (int h = 0; h < 2; h++) {
            float s = 0.f;
            #pragma unroll
            for (int j = 0; j < 4; j++)
                #pragma unroll
                for (int i = 0; i < 2; i++) {
                    const float e = fexp(c[mt][j][2 * h + i]);
                    c[mt][j][2 * h + i] = e;
                    s += e;
                }
            s += __shfl_xor_sync(0xffffffffu, s, 1);
            s += __shfl_xor_sync(0xffffffffu, s, 2);
            const float inv = __fdividef(1.0f, s);
            // position (j,i) holds true col 8c+2j+i == float index 2j+i of m4
            const float* mf = (const float*)&m4[2 * mt + h][0];
            #pragma unroll
            for (int j = 0; j < 4; j++)
                #pragma unroll
                for (int i = 0; i < 2; i++)
                    c[mt][j][2 * h + i] *= inv * mf[2 * j + i];
        }

    // ---- AV: O = P @ Xb; B rows pi-permuted (k matches P), cols pair-
    //      transposed (n) so output position p holds true col perm(p) ----
    float o[2][4][4];
    #pragma unroll
    for (int mt = 0; mt < 2; mt++)
        #pragma unroll
        for (int j = 0; j < 4; j++)
            o[mt][j][0] = o[mt][j][1] = o[mt][j][2] = o[mt][j][3] = 0.f;

    #pragma unroll
    for (int kt = 0; kt < 2; kt++) {
        u32 PH[2][4], PL[2][4];
        #pragma unroll
        for (int mt = 0; mt < 2; mt++) {
            const float* d0 = c[mt][2 * kt];
            const float* d1 = c[mt][2 * kt + 1];
            PH[mt][0] = pk_bf16(d0[0], d0[1]);
            PH[mt][1] = pk_bf16(d0[2], d0[3]);
            PH[mt][2] = pk_bf16(d1[0], d1[1]);
            PH[mt][3] = pk_bf16(d1[2], d1[3]);
            PL[mt][0] = pk_bf16(d0[0] - bf16_rt(d0[0]), d0[1] - bf16_rt(d0[1]));
            PL[mt][1] = pk_bf16(d0[2] - bf16_rt(d0[2]), d0[3] - bf16_rt(d0[3]));
            PL[mt][2] = pk_bf16(d1[0] - bf16_rt(d1[0]), d1[1] - bf16_rt(d1[1]));
            PL[mt][3] = pk_bf16(d1[2] - bf16_rt(d1[2]), d1[3] - bf16_rt(d1[3]));
        }
        u32 BH[2][4], BL[2][4];
        LDM4T(BH[0], XtH + kt * 1280 + toff);
        LDM4T(BH[1], XtH + kt * 1280 + 32 + toff);
        LDM4T(BL[0], XtL + kt * 1280 + toff);
        LDM4T(BL[1], XtL + kt * 1280 + 32 + toff);
        #pragma unroll
        for (int mt = 0; mt < 2; mt++)
            #pragma unroll
            for (int j = 0; j < 4; j++) {
                const int jp = j >> 1, s = (j & 1) * 2;
                MMA(o[mt][j], PH[mt], BH[jp][s], BH[jp][s + 1]);
                MMA(o[mt][j], PL[mt], BH[jp][s], BH[jp][s + 1]);
                MMA(o[mt][j], PH[mt], BL[jp][s], BL[jp][s + 1]);
            }
    }

    // ---- output: lane-quad owns true cols [8c,8c+8) -> STG.128 pairs ----
    #pragma unroll
    for (int mt = 0; mt < 2; mt++)
        #pragma unroll
        for (int h = 0; h < 2; h++) {
            float* orow = out + blkoff + (size_t)(16 * mt + 8 * h + (l >> 2)) * 32 + 8 * (l & 3);
            *(float4*)(orow)     = make_float4(o[mt][0][2 * h], o[mt][0][2 * h + 1],
                                               o[mt][1][2 * h], o[mt][1][2 * h + 1]);
            *(float4*)(orow + 4) = make_float4(o[mt][2][2 * h], o[mt][2][2 * h + 1],
                                               o[mt][3][2 * h], o[mt][3][2 * h + 1]);
        }
}

extern "C" void kernel_launch(void* const* d_in, const int* in_sizes, int n_in,
                              void* d_out, int out_size) {
    const float* x1   = (const float*)d_in[0];   // (1,384,32,32)
    const float* mask = (const float*)d_in[1];   // (384,384,32,32)
    float* out = (float*)d_out;                  // (384,384,32,32)
    (void)in_sizes; (void)n_in; (void)out_size;

    prep_kernel<<<96, 128>>>(x1);                       // 12288 rows
    dim3 grid(NN / 2, NN / 2, 1);                       // 4 pairs per CTA
    attn_mma_kernel<<<grid, 128>>>(mask, out);
}

// round 15
// speedup vs baseline: 1.3667x; 1.2066x over previous
#include <cuda_runtime.h>
#include <cuda_bf16.h>

// out[a,b] = (softmax(X[b] @ X[a]^T) * mask[a,b]) @ X[b]
// X: (384,32,32) fp32; mask/out: (384,384,32,32) fp32.
//
// mma.sync (HMMA fallback) path; tcgen05 unreachable (compute_103 PTX).
// R15 = R7 base + FREE pi only:
//   - Xb and Xa staged with pi-permuted source rows (no new arrays/traffic).
//   - qk n-position (j,c,i) holds true a-col 8c+2j+i -> mask via dense
//     LDG.128 (half the wavefronts).
//   - qk/out m-rows are pi-permuted -> pure index remap at mask-read/STG:
//     row-position 16mt+8h+q maps to true row 8*((q>>1)&3)+(q&1)+2*(2mt+h).
//   - AV's B k-rows (ldmatrix.trans on the same Xb array) are pi-permuted,
//     matching P's pi-permuted k-columns exactly.

#define NN 384
#define RS   80          // smem row stride (bytes)
#define BLKB (32 * RS)   // one 32-row array: 2560 B

typedef unsigned int u32;

// [hi 64B | lo 64B] per row, 384*32 rows = 1.5 MB (L2-resident scratch)
__device__ uint4 Xsplit[384 * 32 * 8];

static __device__ __forceinline__ u32 smem_u32(const void* p) {
    u32 a;
    asm("{ .reg .u64 t; cvta.to.shared.u64 t, %1; cvt.u32.u64 %0, t; }" : "=r"(a) : "l"(p));
    return a;
}

#define LDM4(r, addr)                                                                   \
    asm volatile("ldmatrix.sync.aligned.m8n8.x4.shared.b16 {%0,%1,%2,%3}, [%4];"        \
                 : "=r"((r)[0]), "=r"((r)[1]), "=r"((r)[2]), "=r"((r)[3]) : "r"(addr))

#define LDM4T(r, addr)                                                                  \
    asm volatile("ldmatrix.sync.aligned.m8n8.x4.trans.shared.b16 {%0,%1,%2,%3}, [%4];"  \
                 : "=r"((r)[0]), "=r"((r)[1]), "=r"((r)[2]), "=r"((r)[3]) : "r"(addr))

#define MMA(c, a, b0, b1)                                                               \
    asm volatile("mma.sync.aligned.m16n8k16.row.col.f32.bf16.bf16.f32 "                 \
                 "{%0,%1,%2,%3}, {%4,%5,%6,%7}, {%8,%9}, {%0,%1,%2,%3};"                \
                 : "+f"((c)[0]), "+f"((c)[1]), "+f"((c)[2]), "+f"((c)[3])               \
                 : "r"((a)[0]), "r"((a)[1]), "r"((a)[2]), "r"((a)[3]), "r"(b0), "r"(b1))

static __device__ __forceinline__ u32 pk_bf16(float lo, float hi) {
    u32 r;  // low half <- 'lo' (even element)
    asm("cvt.rn.bf16x2.f32 %0, %1, %2;" : "=r"(r) : "f"(hi), "f"(lo));
    return r;
}
static __device__ __forceinline__ float bf16_rt(float x) {
    return __bfloat162float(__float2bfloat16(x));
}

// pi: position p = 8j+2c+i  ->  true index 8c+2j+i  (involution)
static __device__ __forceinline__ int perm(int p) {
    return 8 * ((p >> 1) & 3) + 2 * (p >> 3) + (p & 1);
}

// exp via deg-5 2^f poly; FMA pipe only.
static __device__ __forceinline__ float fexp(float x) {
    x = fmaxf(x, -87.0f);
    const float z = x * 1.4426950408889634f;
    const int   i = __float2int_rn(z);
    const float f = z - __int2float_rn(i);
    float p = 0.0013333558f;
    p = fmaf(p, f, 0.0096181291f);
    p = fmaf(p, f, 0.0555041087f);
    p = fmaf(p, f, 0.2402265070f);
    p = fmaf(p, f, 0.6931471806f);
    p = fmaf(p, f, 1.0f);
    return p * __int_as_float((i + 127) << 23);
}

// ---- prep: split all X rows into bf16 hi/lo once ----
__global__ __launch_bounds__(128)
void prep_kernel(const float* __restrict__ x1) {
    const int idx = blockIdx.x * 128 + threadIdx.x;   // row 0..12287
    const float4* src = (const float4*)(x1 + (size_t)idx * 32);
    float v[32];
    #pragma unroll
    for (int j = 0; j < 8; j++) {
        const float4 q = src[j];
        v[4 * j] = q.x; v[4 * j + 1] = q.y; v[4 * j + 2] = q.z; v[4 * j + 3] = q.w;
    }
    uint4* dst = Xsplit + (size_t)idx * 8;
    #pragma unroll
    for (int c = 0; c < 4; c++) {
        const float* g = v + 8 * c;
        uint4 hv, lv;
        hv.x = pk_bf16(g[0], g[1]); hv.y = pk_bf16(g[2], g[3]);
        hv.z = pk_bf16(g[4], g[5]); hv.w = pk_bf16(g[6], g[7]);
        float r[8];
        #pragma unroll
        for (int i = 0; i < 8; i++) r[i] = g[i] - bf16_rt(g[i]);
        lv.x = pk_bf16(r[0], r[1]); lv.y = pk_bf16(r[2], r[3]);
        lv.z = pk_bf16(r[4], r[5]); lv.w = pk_bf16(r[6], r[7]);
        dst[c] = hv;
        dst[4 + c] = lv;
    }
}

static __device__ __forceinline__ void stage_row(char* sm, int arr, int l,
                                                 const uint4* g) {
    char* H = sm + arr * BLKB + l * RS;
    char* L = H + BLKB;
    const int rot = l >> 3;
    #pragma unroll
    for (int c = 0; c < 4; c++) {
        const int cc = (c + rot) & 3;
        *(uint4*)(H + cc * 16) = g[cc];
        *(uint4*)(L + cc * 16) = g[4 + cc];
    }
}

__global__ __launch_bounds__(128, 7)
void attn_mma_kernel(const float* __restrict__ mask,
                     float* __restrict__ out) {
    // arrays: [0..3] Xb{0,1} hi/lo, [4..7] Xa{0,1} hi/lo  (all pi-row-staged)
    __shared__ __align__(16) char sm[8 * BLKB];   // 20480 B

    const int t = threadIdx.x;
    const int w = t >> 5;
    const int l = t & 31;
    const int bx = blockIdx.x, by = blockIdx.y;
    const int pl = perm(l);

    // ---- staging: warp w stages block w, smem row l <- X row perm(l) ----
    {
        const int blk  = w;                // 0,1 = b-blocks; 2,3 = a-blocks
        const int gblk = (blk < 2) ? (2 * bx + blk) : (2 * by + (blk - 2));
        const uint4* g = Xsplit + ((size_t)gblk * 32 + pl) * 8;
        stage_row((char*)sm, blk * 2, l, g);
    }
    __syncthreads();

    // ---- per-warp pair ----
    const int ai = w >> 1, bi = w & 1;
    const int a = 2 * by + ai, b = 2 * bx + bi;
    const size_t blkoff = ((size_t)a * NN + b) * 1024;

    const u32 sb = smem_u32(sm);
    const u32 XbH = sb + (bi * 2) * BLKB,      XbL = XbH + BLKB;
    const u32 XaH = sb + (4 + ai * 2) * BLKB,  XaL = XaH + BLKB;

    // ldmatrix per-lane offsets (consecutive-row patterns, conflict-free)
    const u32 aoff = (((l >> 3) & 1) * 8 + (l & 7)) * RS + ((l >> 4) & 1) * 16;
    const u32 boff = ((l >> 4) * 8 + (l & 7)) * RS + ((l >> 3) & 1) * 16;
    const u32 toff = (l & 15) * RS + ((l >> 4) & 1) * 16;

    // pi'd row base for mask/out: row-position 16mt+8h+q -> true row brow+2g
    const int q    = l >> 2;
    const int brow = 8 * ((q >> 1) & 3) + (q & 1);

    // mask: lane-quad c owns true cols [8c,8c+8) at true row brow+2g
    const float* mbase = mask + blkoff + (size_t)brow * 32 + 8 * (l & 3);

    // mask prefetch FIRST HALF (groups g=0,1): dense LDG.128 pairs
    float4 m4[4][2];
    #pragma unroll
    for (int g = 0; g < 2; g++) {
        m4[g][0] = *(const float4*)(mbase + (size_t)(2 * g) * 32);
        m4[g][1] = *(const float4*)(mbase + (size_t)(2 * g) * 32 + 4);
    }

    // ---- QK: 3-term bf16 split (both operands pi-row-staged) ----
    float c[2][4][4];
    #pragma unroll
    for (int mt = 0; mt < 2; mt++)
        #pragma unroll
        for (int j = 0; j < 4; j++)
            c[mt][j][0] = c[mt][j][1] = c[mt][j][2] = c[mt][j][3] = 0.f;

    #pragma unroll
    for (int kt = 0; kt < 2; kt++) {
        u32 AH[2][4], AL[2][4], BH[2][4], BL[2][4];
        LDM4(AH[0], XbH + kt * 32 + aoff);
        LDM4(AH[1], XbH + 1280 + kt * 32 + aoff);
        LDM4(AL[0], XbL + kt * 32 + aoff);
        LDM4(AL[1], XbL + 1280 + kt * 32 + aoff);
        LDM4(BH[0], XaH + kt * 32 + boff);
        LDM4(BH[1], XaH + 1280 + kt * 32 + boff);
        LDM4(BL[0], XaL + kt * 32 + boff);
        LDM4(BL[1], XaL + 1280 + kt * 32 + boff);
        #pragma unroll
        for (int mt = 0; mt < 2; mt++)
            #pragma unroll
            for (int j = 0; j < 4; j++) {
                const int jp = j >> 1, s = (j & 1) * 2;
                MMA(c[mt][j], AH[mt], BH[jp][s], BH[jp][s + 1]);
                MMA(c[mt][j], AL[mt], BH[jp][s], BH[jp][s + 1]);
                MMA(c[mt][j], AH[mt], BL[jp][s], BL[jp][s + 1]);
            }
    }

    // mask prefetch SECOND HALF (groups g=2,3)
    #pragma unroll
    for (int g = 2; g < 4; g++) {
        m4[g][0] = *(const float4*)(mbase + (size_t)(2 * g) * 32);
        m4[g][1] = *(const float4*)(mbase + (size_t)(2 * g) * 32 + 4);
    }

    // ---- softmax (rows complete per fragment row) + dropout ----
    #pragma unroll
    for (int mt = 0; mt < 2; mt++)
        #pragma unroll
        for (int h = 0; h < 2; h++) {
            float s = 0.f;
            #pragma unroll
            for (int j = 0; j < 4; j++)
                #pragma unroll
                for (int i = 0; i < 2; i++) {
                    const float e = fexp(c[mt][j][2 * h + i]);
                    c[mt][j][2 * h + i] = e;
                    s += e;
                }
            s += __shfl_xor_sync(0xffffffffu, s, 1);
            s += __shfl_xor_sync(0xffffffffu, s, 2);
            const float inv = __fdividef(1.0f, s);
            // n-position (j,i) holds true col 8c+2j+i == float index 2j+i
            const float* mf = (const float*)&m4[2 * mt + h][0];
            #pragma unroll
            for (int j = 0; j < 4; j++)
                #pragma unroll
                for (int i = 0; i < 2; i++)
                    c[mt][j][2 * h + i] *= inv * mf[2 * j + i];
        }

    // ---- AV: O = P @ Xb; B via ldmatrix.trans on the pi-row-staged Xb,
    //      whose k-row order matches P's pi-permuted k-columns ----
    float o[2][4][4];
    #pragma unroll
    for (int mt = 0; mt < 2; mt++)
        #pragma unroll
        for (int j = 0; j < 4; j++)
            o[mt][j][0] = o[mt][j][1] = o[mt][j][2] = o[mt][j][3] = 0.f;

    #pragma unroll
    for (int kt = 0; kt < 2; kt++) {
        u32 PH[2][4], PL[2][4];
        #pragma unroll
        for (int mt = 0; mt < 2; mt++) {
            const float* d0 = c[mt][2 * kt];
            const float* d1 = c[mt][2 * kt + 1];
            PH[mt][0] = pk_bf16(d0[0], d0[1]);
            PH[mt][1] = pk_bf16(d0[2], d0[3]);
            PH[mt][2] = pk_bf16(d1[0], d1[1]);
            PH[mt][3] = pk_bf16(d1[2], d1[3]);
            PL[mt][0] = pk_bf16(d0[0] - bf16_rt(d0[0]), d0[1] - bf16_rt(d0[1]));
            PL[mt][1] = pk_bf16(d0[2] - bf16_rt(d0[2]), d0[3] - bf16_rt(d0[3]));
            PL[mt][2] = pk_bf16(d1[0] - bf16_rt(d1[0]), d1[1] - bf16_rt(d1[1]));
            PL[mt][3] = pk_bf16(d1[2] - bf16_rt(d1[2]), d1[3] - bf16_rt(d1[3]));
        }
        u32 BH[2][4], BL[2][4];
        LDM4T(BH[0], XbH + kt * 1280 + toff);        // out-cols j 0..15
        LDM4T(BH[1], XbH + kt * 1280 + 32 + toff);   // out-cols j 16..31
        LDM4T(BL[0], XbL + kt * 1280 + toff);
        LDM4T(BL[1], XbL + kt * 1280 + 32 + toff);
        #pragma unroll
        for (int mt = 0; mt < 2; mt++)
            #pragma unroll
            for (int j = 0; j < 4; j++) {
                const int jp = j >> 1, s = (j & 1) * 2;
                MMA(o[mt][j], PH[mt], BH[jp][s], BH[jp][s + 1]);
                MMA(o[mt][j], PL[mt], BH[jp][s], BH[jp][s + 1]);
                MMA(o[mt][j], PH[mt], BL[jp][s], BL[jp][s + 1]);
            }
    }

    // ---- output: true row brow+2(2mt+h), natural cols 8j+2c -> STG.64 ----
    #pragma unroll
    for (int mt = 0; mt < 2; mt++)
        #pragma unroll
        for (int h = 0; h < 2; h++) {
            float* orow = out + blkoff + (size_t)(brow + 2 * (2 * mt + h)) * 32 + 2 * (l & 3);
            #pragma unroll
            for (int j = 0; j < 4; j++)
                *(float2*)(orow + 8 * j) = make_float2(o[mt][j][2 * h], o[mt][j][2 * h + 1]);
        }
}

extern "C" void kernel_launch(void* const* d_in, const int* in_sizes, int n_in,
                              void* d_out, int out_size) {
    const float* x1   = (const float*)d_in[0];   // (1,384,32,32)
    const float* mask = (const float*)d_in[1];   // (384,384,32,32)
    float* out = (float*)d_out;                  // (384,384,32,32)
    (void)in_sizes; (void)n_in; (void)out_size;

    prep_kernel<<<96, 128>>>(x1);                       // 12288 rows
    dim3 grid(NN / 2, NN / 2, 1);                       // 4 pairs per CTA
    attn_mma_kernel<<<grid, 128>>>(mask, out);
}

// round 16
// speedup vs baseline: 1.4482x; 1.0596x over previous
#include <cuda_runtime.h>
#include <cuda_bf16.h>

// out[a,b] = (softmax(X[b] @ X[a]^T) * mask[a,b]) @ X[b]
// X: (384,32,32) fp32; mask/out: (384,384,32,32) fp32.
//
// mma.sync (HMMA fallback) path; tcgen05 unreachable (compute_103 PTX).
// R16 = R15 + head-dim pi as the GLOBAL storage layout (single array):
//   - prep stores X with head columns pair-transposed (u32 slot 4j+c <-
//     slot 4c+j), i.e. element position p holds true head col pi(p).
//   - QK invariant: A and B k-columns permuted identically.
//   - AV B n-columns pi-permuted -> output position p holds true col pi(p)
//     -> contiguous 8-col block per lane-quad -> out via STG.128.
//   - rows pi-permuted at staging (as R15) -> mask via dense LDG.128.
// Staging cost identical to R15; only the out store gets denser.

#define NN 384
#define RS   80          // smem row stride (bytes)
#define BLKB (32 * RS)   // one 32-row array: 2560 B

typedef unsigned int u32;

// [hi 64B | lo 64B] per row, head cols pair-transposed; 1.5 MB (L2-resident)
__device__ uint4 XsplitCT[384 * 32 * 8];

static __device__ __forceinline__ u32 smem_u32(const void* p) {
    u32 a;
    asm("{ .reg .u64 t; cvta.to.shared.u64 t, %1; cvt.u32.u64 %0, t; }" : "=r"(a) : "l"(p));
    return a;
}

#define LDM4(r, addr)                                                                   \
    asm volatile("ldmatrix.sync.aligned.m8n8.x4.shared.b16 {%0,%1,%2,%3}, [%4];"        \
                 : "=r"((r)[0]), "=r"((r)[1]), "=r"((r)[2]), "=r"((r)[3]) : "r"(addr))

#define LDM4T(r, addr)                                                                  \
    asm volatile("ldmatrix.sync.aligned.m8n8.x4.trans.shared.b16 {%0,%1,%2,%3}, [%4];"  \
                 : "=r"((r)[0]), "=r"((r)[1]), "=r"((r)[2]), "=r"((r)[3]) : "r"(addr))

#define MMA(c, a, b0, b1)                                                               \
    asm volatile("mma.sync.aligned.m16n8k16.row.col.f32.bf16.bf16.f32 "                 \
                 "{%0,%1,%2,%3}, {%4,%5,%6,%7}, {%8,%9}, {%0,%1,%2,%3};"                \
                 : "+f"((c)[0]), "+f"((c)[1]), "+f"((c)[2]), "+f"((c)[3])               \
                 : "r"((a)[0]), "r"((a)[1]), "r"((a)[2]), "r"((a)[3]), "r"(b0), "r"(b1))

static __device__ __forceinline__ u32 pk_bf16(float lo, float hi) {
    u32 r;  // low half <- 'lo' (even element)
    asm("cvt.rn.bf16x2.f32 %0, %1, %2;" : "=r"(r) : "f"(hi), "f"(lo));
    return r;
}
static __device__ __forceinline__ float bf16_rt(float x) {
    return __bfloat162float(__float2bfloat16(x));
}

// pi: position p = 8j+2c+i  ->  true index 8c+2j+i  (involution)
static __device__ __forceinline__ int perm(int p) {
    return 8 * ((p >> 1) & 3) + 2 * (p >> 3) + (p & 1);
}

// exp via deg-5 2^f poly; FMA pipe only.
static __device__ __forceinline__ float fexp(float x) {
    x = fmaxf(x, -87.0f);
    const float z = x * 1.4426950408889634f;
    const int   i = __float2int_rn(z);
    const float f = z - __int2float_rn(i);
    float p = 0.0013333558f;
    p = fmaf(p, f, 0.0096181291f);
    p = fmaf(p, f, 0.0555041087f);
    p = fmaf(p, f, 0.2402265070f);
    p = fmaf(p, f, 0.6931471806f);
    p = fmaf(p, f, 1.0f);
    return p * __int_as_float((i + 127) << 23);
}

// ---- prep: bf16 hi/lo split with head cols pair-transposed (pi layout) ----
__global__ __launch_bounds__(128)
void prep_kernel(const float* __restrict__ x1) {
    const int idx = blockIdx.x * 128 + threadIdx.x;   // row 0..12287
    const float4* src = (const float4*)(x1 + (size_t)idx * 32);
    float v[32], r[32];
    #pragma unroll
    for (int j = 0; j < 8; j++) {
        const float4 q = src[j];
        v[4 * j] = q.x; v[4 * j + 1] = q.y; v[4 * j + 2] = q.z; v[4 * j + 3] = q.w;
    }
    #pragma unroll
    for (int i = 0; i < 32; i++) r[i] = v[i] - bf16_rt(v[i]);

    uint4* dct = XsplitCT + (size_t)idx * 8;
    #pragma unroll
    for (int c = 0; c < 4; c++) {
        // chunk c slot j holds true cols (8j+2c, 8j+2c+1): position p -> pi(p)
        dct[c]     = make_uint4(pk_bf16(v[2 * c], v[2 * c + 1]),
                                pk_bf16(v[8 + 2 * c], v[8 + 2 * c + 1]),
                                pk_bf16(v[16 + 2 * c], v[16 + 2 * c + 1]),
                                pk_bf16(v[24 + 2 * c], v[24 + 2 * c + 1]));
        dct[4 + c] = make_uint4(pk_bf16(r[2 * c], r[2 * c + 1]),
                                pk_bf16(r[8 + 2 * c], r[8 + 2 * c + 1]),
                                pk_bf16(r[16 + 2 * c], r[16 + 2 * c + 1]),
                                pk_bf16(r[24 + 2 * c], r[24 + 2 * c + 1]));
    }
}

static __device__ __forceinline__ void stage_row(char* sm, int arr, int l,
                                                 const uint4* g) {
    char* H = sm + arr * BLKB + l * RS;
    char* L = H + BLKB;
    const int rot = l >> 3;
    #pragma unroll
    for (int c = 0; c < 4; c++) {
        const int cc = (c + rot) & 3;
        *(uint4*)(H + cc * 16) = g[cc];
        *(uint4*)(L + cc * 16) = g[4 + cc];
    }
}

__global__ __launch_bounds__(128, 7)
void attn_mma_kernel(const float* __restrict__ mask,
                     float* __restrict__ out) {
    // arrays: [0..3] Xb{0,1} hi/lo, [4..7] Xa{0,1} hi/lo  (pi rows, pi cols)
    __shared__ __align__(16) char sm[8 * BLKB];   // 20480 B

    const int t = threadIdx.x;
    const int w = t >> 5;
    const int l = t & 31;
    const int bx = blockIdx.x, by = blockIdx.y;
    const int pl = perm(l);

    // ---- staging: warp w stages block w, smem row l <- X row perm(l) ----
    {
        const int blk  = w;                // 0,1 = b-blocks; 2,3 = a-blocks
        const int gblk = (blk < 2) ? (2 * bx + blk) : (2 * by + (blk - 2));
        const uint4* g = XsplitCT + ((size_t)gblk * 32 + pl) * 8;
        stage_row((char*)sm, blk * 2, l, g);
    }
    __syncthreads();

    // ---- per-warp pair ----
    const int ai = w >> 1, bi = w & 1;
    const int a = 2 * by + ai, b = 2 * bx + bi;
    const size_t blkoff = ((size_t)a * NN + b) * 1024;

    const u32 sb = smem_u32(sm);
    const u32 XbH = sb + (bi * 2) * BLKB,      XbL = XbH + BLKB;
    const u32 XaH = sb + (4 + ai * 2) * BLKB,  XaL = XaH + BLKB;

    // ldmatrix per-lane offsets (consecutive-row patterns, conflict-free)
    const u32 aoff = (((l >> 3) & 1) * 8 + (l & 7)) * RS + ((l >> 4) & 1) * 16;
    const u32 boff = ((l >> 4) * 8 + (l & 7)) * RS + ((l >> 3) & 1) * 16;
    const u32 toff = (l & 15) * RS + ((l >> 4) & 1) * 16;

    // pi'd row base for mask/out: row-position 16mt+8h+q -> true row brow+2g
    const int q    = l >> 2;
    const int brow = 8 * ((q >> 1) & 3) + (q & 1);

    // mask: lane-quad c owns true cols [8c,8c+8) at true row brow+2g
    const float* mbase = mask + blkoff + (size_t)brow * 32 + 8 * (l & 3);

    // mask prefetch FIRST HALF (groups g=0,1): dense LDG.128 pairs
    float4 m4[4][2];
    #pragma unroll
    for (int g = 0; g < 2; g++) {
        m4[g][0] = *(const float4*)(mbase + (size_t)(2 * g) * 32);
        m4[g][1] = *(const float4*)(mbase + (size_t)(2 * g) * 32 + 4);
    }

    // ---- QK: 3-term bf16 split (k-cols permuted identically -> invariant) ----
    float c[2][4][4];
    #pragma unroll
    for (int mt = 0; mt < 2; mt++)
        #pragma unroll
        for (int j = 0; j < 4; j++)
            c[mt][j][0] = c[mt][j][1] = c[mt][j][2] = c[mt][j][3] = 0.f;

    #pragma unroll
    for (int kt = 0; kt < 2; kt++) {
        u32 AH[2][4], AL[2][4], BH[2][4], BL[2][4];
        LDM4(AH[0], XbH + kt * 32 + aoff);
        LDM4(AH[1], XbH + 1280 + kt * 32 + aoff);
        LDM4(AL[0], XbL + kt * 32 + aoff);
        LDM4(AL[1], XbL + 1280 + kt * 32 + aoff);
        LDM4(BH[0], XaH + kt * 32 + boff);
        LDM4(BH[1], XaH + 1280 + kt * 32 + boff);
        LDM4(BL[0], XaL + kt * 32 + boff);
        LDM4(BL[1], XaL + 1280 + kt * 32 + boff);
        #pragma unroll
        for (int mt = 0; mt < 2; mt++)
            #pragma unroll
            for (int j = 0; j < 4; j++) {
                const int jp = j >> 1, s = (j & 1) * 2;
                MMA(c[mt][j], AH[mt], BH[jp][s], BH[jp][s + 1]);
                MMA(c[mt][j], AL[mt], BH[jp][s], BH[jp][s + 1]);
                MMA(c[mt][j], AH[mt], BL[jp][s], BL[jp][s + 1]);
            }
    }

    // mask prefetch SECOND HALF (groups g=2,3)
    #pragma unroll
    for (int g = 2; g < 4; g++) {
        m4[g][0] = *(const float4*)(mbase + (size_t)(2 * g) * 32);
        m4[g][1] = *(const float4*)(mbase + (size_t)(2 * g) * 32 + 4);
    }

    // ---- softmax + dropout ----
    #pragma unroll
    for (int mt = 0; mt < 2; mt++)
        #pragma unroll
        for (int h = 0; h < 2; h++) {
            float s = 0.f;
            #pragma unroll
            for (int j = 0; j < 4; j++)
                #pragma unroll
                for (int i = 0; i < 2; i++) {
                    const float e = fexp(c[mt][j][2 * h + i]);
                    c[mt][j][2 * h + i] = e;
                    s += e;
                }
            s += __shfl_xor_sync(0xffffffffu, s, 1);
            s += __shfl_xor_sync(0xffffffffu, s, 2);
            const float inv = __fdividef(1.0f, s);
            // n-position (j,i) holds true a-col 8c+2j+i == float index 2j+i
            const float* mf = (const float*)&m4[2 * mt + h][0];
            #pragma unroll
            for (int j = 0; j < 4; j++)
                #pragma unroll
                for (int i = 0; i < 2; i++)
                    c[mt][j][2 * h + i] *= inv * mf[2 * j + i];
        }

    // ---- AV: O = P @ Xb; B k-rows pi-staged (match P), B n-cols pi-stored
    //      -> output position p holds true col pi(p) ----
    float o[2][4][4];
    #pragma unroll
    for (int mt = 0; mt < 2; mt++)
        #pragma unroll
        for (int j = 0; j < 4; j++)
            o[mt][j][0] = o[mt][j][1] = o[mt][j][2] = o[mt][j][3] = 0.f;

    #pragma unroll
    for (int kt = 0; kt < 2; kt++) {
        u32 PH[2][4], PL[2][4];
        #pragma unroll
        for (int mt = 0; mt < 2; mt++) {
            const float* d0 = c[mt][2 * kt];
            const float* d1 = c[mt][2 * kt + 1];
            PH[mt][0] = pk_bf16(d0[0], d0[1]);
            PH[mt][1] = pk_bf16(d0[2], d0[3]);
            PH[mt][2] = pk_bf16(d1[0], d1[1]);
            PH[mt][3] = pk_bf16(d1[2], d1[3]);
            PL[mt][0] = pk_bf16(d0[0] - bf16_rt(d0[0]), d0[1] - bf16_rt(d0[1]));
            PL[mt][1] = pk_bf16(d0[2] - bf16_rt(d0[2]), d0[3] - bf16_rt(d0[3]));
            PL[mt][2] = pk_bf16(d1[0] - bf16_rt(d1[0]), d1[1] - bf16_rt(d1[1]));
            PL[mt][3] = pk_bf16(d1[2] - bf16_rt(d1[2]), d1[3] - bf16_rt(d1[3]));
        }
        u32 BH[2][4], BL[2][4];
        LDM4T(BH[0], XbH + kt * 1280 + toff);
        LDM4T(BH[1], XbH + kt * 1280 + 32 + toff);
        LDM4T(BL[0], XbL + kt * 1280 + toff);
        LDM4T(BL[1], XbL + kt * 1280 + 32 + toff);
        #pragma unroll
        for (int mt = 0; mt < 2; mt++)
            #pragma unroll
            for (int j = 0; j < 4; j++) {
                const int jp = j >> 1, s = (j & 1) * 2;
                MMA(o[mt][j], PH[mt], BH[jp][s], BH[jp][s + 1]);
                MMA(o[mt][j], PL[mt], BH[jp][s], BH[jp][s + 1]);
                MMA(o[mt][j], PH[mt], BL[jp][s], BL[jp][s + 1]);
            }
    }

    // ---- output: true row brow+2(2mt+h), lane-quad owns true cols
    //      [8c,8c+8) -> two STG.128 per (mt,h) ----
    #pragma unroll
    for (int mt = 0; mt < 2; mt++)
        #pragma unroll
        for (int h = 0; h < 2; h++) {
            float* orow = out + blkoff + (size_t)(brow + 2 * (2 * mt + h)) * 32 + 8 * (l & 3);
            *(float4*)(orow)     = make_float4(o[mt][0][2 * h], o[mt][0][2 * h + 1],
                                               o[mt][1][2 * h], o[mt][1][2 * h + 1]);
            *(float4*)(orow + 4) = make_float4(o[mt][2][2 * h], o[mt][2][2 * h + 1],
                                               o[mt][3][2 * h], o[mt][3][2 * h + 1]);
        }
}

extern "C" void kernel_launch(void* const* d_in, const int* in_sizes, int n_in,
                              void* d_out, int out_size) {
    const float* x1   = (const float*)d_in[0];   // (1,384,32,32)
    const float* mask = (const float*)d_in[1];   // (384,384,32,32)
    float* out = (float*)d_out;                  // (384,384,32,32)
    (void)in_sizes; (void)n_in; (void)out_size;

    prep_kernel<<<96, 128>>>(x1);                       // 12288 rows
    dim3 grid(NN / 2, NN / 2, 1);                       // 4 pairs per CTA
    attn_mma_kernel<<<grid, 128>>>(mask, out);
}

// round 17
// speedup vs baseline: 1.9006x; 1.3124x over previous
#include <cuda_runtime.h>
#include <cuda_bf16.h>

// out[a,b] = (softmax(X[b] @ X[a]^T) * mask[a,b]) @ X[b]
// X: (384,32,32) fp32; mask/out: (384,384,32,32) fp32.
//
// mma.sync (HMMA fallback) path; tcgen05 unreachable (compute_103 PTX).
// R17 = R16 (pi rows + pi head-cols, dense mask/out) +
//   - 4x4 CTA tile: 256 thr / 8 warps; warp w owns b-block (w&3) and loops
//     over 2 a-blocks (2*(w>>2)+p). 8 staged blocks serve 16 pairs (staging
//     amortization 2x, Xsplit L2 traffic 2x down).
//   - coalesced conflict-free staging: XsplitCT slots pre-permuted by pi in
//     prep (pi is an involution), so staging reads slots naturally; lane
//     (r,c) copies full 128B rows in groups of 4 -> LDG 4 lines/inst (4 wf)
//     and STS exactly 4 words/bank (4 wf).

#define NN 384
#define RS   80          // smem row stride (bytes)
#define BLKB (32 * RS)   // one 32-row array: 2560 B

typedef unsigned int u32;

// [hi 64B | lo 64B] per row, head cols pair-transposed, rows pre-permuted by
// pi within each block; 1.5 MB (L2-resident scratch)
__device__ uint4 XsplitCT[384 * 32 * 8];

static __device__ __forceinline__ u32 smem_u32(const void* p) {
    u32 a;
    asm("{ .reg .u64 t; cvta.to.shared.u64 t, %1; cvt.u32.u64 %0, t; }" : "=r"(a) : "l"(p));
    return a;
}

#define LDM4(r, addr)                                                                   \
    asm volatile("ldmatrix.sync.aligned.m8n8.x4.shared.b16 {%0,%1,%2,%3}, [%4];"        \
                 : "=r"((r)[0]), "=r"((r)[1]), "=r"((r)[2]), "=r"((r)[3]) : "r"(addr))

#define LDM4T(r, addr)                                                                  \
    asm volatile("ldmatrix.sync.aligned.m8n8.x4.trans.shared.b16 {%0,%1,%2,%3}, [%4];"  \
                 : "=r"((r)[0]), "=r"((r)[1]), "=r"((r)[2]), "=r"((r)[3]) : "r"(addr))

#define MMA(c, a, b0, b1)                                                               \
    asm volatile("mma.sync.aligned.m16n8k16.row.col.f32.bf16.bf16.f32 "                 \
                 "{%0,%1,%2,%3}, {%4,%5,%6,%7}, {%8,%9}, {%0,%1,%2,%3};"                \
                 : "+f"((c)[0]), "+f"((c)[1]), "+f"((c)[2]), "+f"((c)[3])               \
                 : "r"((a)[0]), "r"((a)[1]), "r"((a)[2]), "r"((a)[3]), "r"(b0), "r"(b1))

static __device__ __forceinline__ u32 pk_bf16(float lo, float hi) {
    u32 r;  // low half <- 'lo' (even element)
    asm("cvt.rn.bf16x2.f32 %0, %1, %2;" : "=r"(r) : "f"(hi), "f"(lo));
    return r;
}
static __device__ __forceinline__ float bf16_rt(float x) {
    return __bfloat162float(__float2bfloat16(x));
}

// pi: position p = 8j+2c+i  ->  true index 8c+2j+i  (involution)
static __device__ __forceinline__ int perm(int p) {
    return 8 * ((p >> 1) & 3) + 2 * (p >> 3) + (p & 1);
}

// exp via deg-5 2^f poly; FMA pipe only.
static __device__ __forceinline__ float fexp(float x) {
    x = fmaxf(x, -87.0f);
    const float z = x * 1.4426950408889634f;
    const int   i = __float2int_rn(z);
    const float f = z - __int2float_rn(i);
    float p = 0.0013333558f;
    p = fmaf(p, f, 0.0096181291f);
    p = fmaf(p, f, 0.0555041087f);
    p = fmaf(p, f, 0.2402265070f);
    p = fmaf(p, f, 0.6931471806f);
    p = fmaf(p, f, 1.0f);
    return p * __int_as_float((i + 127) << 23);
}

// ---- prep: bf16 hi/lo split, head cols pair-transposed, rows pi-slotted ----
__global__ __launch_bounds__(128)
void prep_kernel(const float* __restrict__ x1) {
    const int idx = blockIdx.x * 128 + threadIdx.x;   // X row 0..12287
    const float4* src = (const float4*)(x1 + (size_t)idx * 32);
    float v[32], r[32];
    #pragma unroll
    for (int j = 0; j < 8; j++) {
        const float4 q = src[j];
        v[4 * j] = q.x; v[4 * j + 1] = q.y; v[4 * j + 2] = q.z; v[4 * j + 3] = q.w;
    }
    #pragma unroll
    for (int i = 0; i < 32; i++) r[i] = v[i] - bf16_rt(v[i]);

    // slot perm(row) within the block holds this X row (pi involution)
    const int slot = (idx & ~31) | perm(idx & 31);
    uint4* dct = XsplitCT + (size_t)slot * 8;
    #pragma unroll
    for (int c = 0; c < 4; c++) {
        // chunk c slot j holds true cols (8j+2c, 8j+2c+1): position p -> pi(p)
        dct[c]     = make_uint4(pk_bf16(v[2 * c], v[2 * c + 1]),
                                pk_bf16(v[8 + 2 * c], v[8 + 2 * c + 1]),
                                pk_bf16(v[16 + 2 * c], v[16 + 2 * c + 1]),
                                pk_bf16(v[24 + 2 * c], v[24 + 2 * c + 1]));
        dct[4 + c] = make_uint4(pk_bf16(r[2 * c], r[2 * c + 1]),
                                pk_bf16(r[8 + 2 * c], r[8 + 2 * c + 1]),
                                pk_bf16(r[16 + 2 * c], r[16 + 2 * c + 1]),
                                pk_bf16(r[24 + 2 * c], r[24 + 2 * c + 1]));
    }
}

__global__ __launch_bounds__(256, 3)
void attn_mma_kernel(const float* __restrict__ mask,
                     float* __restrict__ out) {
    // arrays (BLKB units): b-block k -> H=2k, L=2k+1; a-block k -> H=8+2k, L=9+2k
    __shared__ __align__(16) char sm[16 * BLKB];   // 40960 B

    const int t = threadIdx.x;
    const int w = t >> 5;
    const int l = t & 31;
    const int bx = blockIdx.x, by = blockIdx.y;

    // ---- staging: warp w stages one block; coalesced + conflict-free ----
    {
        const int isB  = (w < 4) ? 1 : 0;
        const int gblk = isB ? (4 * bx + w) : (4 * by + (w - 4));
        const int arr  = isB ? (2 * w) : (8 + 2 * (w - 4));
        const uint4* src = XsplitCT + (size_t)gblk * 256;  // 256 uint4 / block
        const int r = l >> 3, c = l & 7;
        const int rofs = 4 * (r & 1) + 16 * (r >> 1);      // {0,4,16,20}
        char* base = sm + arr * BLKB + ((c < 4) ? 0 : BLKB) + 16 * (c & 3);
        #pragma unroll
        for (int i = 0; i < 8; i++) {
            const int row = (i & 3) + 8 * (i >> 2) + rofs;
            *(uint4*)(base + row * RS) = src[row * 8 + c];
        }
    }
    __syncthreads();

    // ---- per-warp: b fixed, loop over 2 a-blocks ----
    const int bi  = w & 3;
    const int ai0 = 2 * (w >> 2);
    const int b   = 4 * bx + bi;

    const u32 sb  = smem_u32(sm);
    const u32 XbH = sb + (2 * bi) * BLKB, XbL = XbH + BLKB;

    // ldmatrix per-lane offsets (consecutive-row patterns, conflict-free)
    const u32 aoff = (((l >> 3) & 1) * 8 + (l & 7)) * RS + ((l >> 4) & 1) * 16;
    const u32 boff = ((l >> 4) * 8 + (l & 7)) * RS + ((l >> 3) & 1) * 16;
    const u32 toff = (l & 15) * RS + ((l >> 4) & 1) * 16;

    // pi'd row base for mask/out: row-position 16mt+8h+q -> true row brow+2g
    const int q    = l >> 2;
    const int brow = 8 * ((q >> 1) & 3) + (q & 1);

    #pragma unroll 1
    for (int p = 0; p < 2; p++) {
        const int ai = ai0 + p;
        const int a  = 4 * by + ai;
        const size_t blkoff = ((size_t)a * NN + b) * 1024;
        const u32 XaH = sb + (8 + 2 * ai) * BLKB, XaL = XaH + BLKB;

        // mask: lane-quad c owns true cols [8c,8c+8) at true row brow+2g
        const float* mbase = mask + blkoff + (size_t)brow * 32 + 8 * (l & 3);

        // mask prefetch FIRST HALF (groups g=0,1): dense LDG.128 pairs
        float4 m4[4][2];
        #pragma unroll
        for (int g = 0; g < 2; g++) {
            m4[g][0] = *(const float4*)(mbase + (size_t)(2 * g) * 32);
            m4[g][1] = *(const float4*)(mbase + (size_t)(2 * g) * 32 + 4);
        }

        // ---- QK: 3-term bf16 split (k-cols permuted identically) ----
        float c4[2][4][4];
        #pragma unroll
        for (int mt = 0; mt < 2; mt++)
            #pragma unroll
            for (int j = 0; j < 4; j++)
                c4[mt][j][0] = c4[mt][j][1] = c4[mt][j][2] = c4[mt][j][3] = 0.f;

        #pragma unroll
        for (int kt = 0; kt < 2; kt++) {
            u32 AH[2][4], AL[2][4], BH[2][4], BL[2][4];
            LDM4(AH[0], XbH + kt * 32 + aoff);
            LDM4(AH[1], XbH + 1280 + kt * 32 + aoff);
            LDM4(AL[0], XbL + kt * 32 + aoff);
            LDM4(AL[1], XbL + 1280 + kt * 32 + aoff);
            LDM4(BH[0], XaH + kt * 32 + boff);
            LDM4(BH[1], XaH + 1280 + kt * 32 + boff);
            LDM4(BL[0], XaL + kt * 32 + boff);
            LDM4(BL[1], XaL + 1280 + kt * 32 + boff);
            #pragma unroll
            for (int mt = 0; mt < 2; mt++)
                #pragma unroll
                for (int j = 0; j < 4; j++) {
                    const int jp = j >> 1, s = (j & 1) * 2;
                    MMA(c4[mt][j], AH[mt], BH[jp][s], BH[jp][s + 1]);
                    MMA(c4[mt][j], AL[mt], BH[jp][s], BH[jp][s + 1]);
                    MMA(c4[mt][j], AH[mt], BL[jp][s], BL[jp][s + 1]);
                }
        }

        // mask prefetch SECOND HALF (groups g=2,3)
        #pragma unroll
        for (int g = 2; g < 4; g++) {
            m4[g][0] = *(const float4*)(mbase + (size_t)(2 * g) * 32);
            m4[g][1] = *(const float4*)(mbase + (size_t)(2 * g) * 32 + 4);
        }

        // ---- softmax + dropout ----
        #pragma unroll
        for (int mt = 0; mt < 2; mt++)
            #pragma unroll
            for (int h = 0; h < 2; h++) {
                float s = 0.f;
                #pragma unroll
                for (int j = 0; j < 4; j++)
                    #pragma unroll
                    for (int i = 0; i < 2; i++) {
                        const float e = fexp(c4[mt][j][2 * h + i]);
                        c4[mt][j][2 * h + i] = e;
                        s += e;
                    }
                s += __shfl_xor_sync(0xffffffffu, s, 1);
                s += __shfl_xor_sync(0xffffffffu, s, 2);
                const float inv = __fdividef(1.0f, s);
                const float* mf = (const float*)&m4[2 * mt + h][0];
                #pragma unroll
                for (int j = 0; j < 4; j++)
                    #pragma unroll
                    for (int i = 0; i < 2; i++)
                        c4[mt][j][2 * h + i] *= inv * mf[2 * j + i];
            }

        // ---- AV: O = P @ Xb; B k-rows pi-staged (match P), B n-cols
        //      pi-stored -> output position p holds true col pi(p) ----
        float o[2][4][4];
        #pragma unroll
        for (int mt = 0; mt < 2; mt++)
            #pragma unroll
            for (int j = 0; j < 4; j++)
                o[mt][j][0] = o[mt][j][1] = o[mt][j][2] = o[mt][j][3] = 0.f;

        #pragma unroll
        for (int kt = 0; kt < 2; kt++) {
            u32 PH[2][4], PL[2][4];
            #pragma unroll
            for (int mt = 0; mt < 2; mt++) {
                const float* d0 = c4[mt][2 * kt];
                const float* d1 = c4[mt][2 * kt + 1];
                PH[mt][0] = pk_bf16(d0[0], d0[1]);
                PH[mt][1] = pk_bf16(d0[2], d0[3]);
                PH[mt][2] = pk_bf16(d1[0], d1[1]);
                PH[mt][3] = pk_bf16(d1[2], d1[3]);
                PL[mt][0] = pk_bf16(d0[0] - bf16_rt(d0[0]), d0[1] - bf16_rt(d0[1]));
                PL[mt][1] = pk_bf16(d0[2] - bf16_rt(d0[2]), d0[3] - bf16_rt(d0[3]));
                PL[mt][2] = pk_bf16(d1[0] - bf16_rt(d1[0]), d1[1] - bf16_rt(d1[1]));
                PL[mt][3] = pk_bf16(d1[2] - bf16_rt(d1[2]), d1[3] - bf16_rt(d1[3]));
            }
            u32 BH[2][4], BL[2][4];
            LDM4T(BH[0], XbH + kt * 1280 + toff);
            LDM4T(BH[1], XbH + kt * 1280 + 32 + toff);
            LDM4T(BL[0], XbL + kt * 1280 + toff);
            LDM4T(BL[1], XbL + kt * 1280 + 32 + toff);
            #pragma unroll
            for (int mt = 0; mt < 2; mt++)
                #pragma unroll
                for (int j = 0; j < 4; j++) {
                    const int jp = j >> 1, s = (j & 1) * 2;
                    MMA(o[mt][j], PH[mt], BH[jp][s], BH[jp][s + 1]);
                    MMA(o[mt][j], PL[mt], BH[jp][s], BH[jp][s + 1]);
                    MMA(o[mt][j], PH[mt], BL[jp][s], BL[jp][s + 1]);
                }
        }

        // ---- output: true row brow+2(2mt+h), lane-quad owns true cols
        //      [8c,8c+8) -> two STG.128 per (mt,h) ----
        #pragma unroll
        for (int mt = 0; mt < 2; mt++)
            #pragma unroll
            for (int h = 0; h < 2; h++) {
                float* orow = out + blkoff + (size_t)(brow + 2 * (2 * mt + h)) * 32 + 8 * (l & 3);
                *(float4*)(orow)     = make_float4(o[mt][0][2 * h], o[mt][0][2 * h + 1],
                                                   o[mt][1][2 * h], o[mt][1][2 * h + 1]);
                *(float4*)(orow + 4) = make_float4(o[mt][2][2 * h], o[mt][2][2 * h + 1],
                                                   o[mt][3][2 * h], o[mt][3][2 * h + 1]);
            }
    }
}

extern "C" void kernel_launch(void* const* d_in, const int* in_sizes, int n_in,
                              void* d_out, int out_size) {
    const float* x1   = (const float*)d_in[0];   // (1,384,32,32)
    const float* mask = (const float*)d_in[1];   // (384,384,32,32)
    float* out = (float*)d_out;                  // (384,384,32,32)
    (void)in_sizes; (void)n_in; (void)out_size;

    prep_kernel<<<96, 128>>>(x1);                       // 12288 rows
    dim3 grid(NN / 4, NN / 4, 1);                       // 96x96 CTAs, 16 pairs
    attn_mma_kernel<<<grid, 256>>>(mask, out);
}